// round 16
// baseline (speedup 1.0000x reference)
#include <cuda_runtime.h>
#include <cstdint>

#define FULL 0xffffffffu
constexpr int NQ  = 8;
constexpr int IND = 512;
constexpr int WPB = 8;            // warps per block
constexpr int TPB = WPB * 32;     // 256
constexpr int M4  = 4;            // batch elements per warp (one pass each)

__global__ __launch_bounds__(TPB, 2)        // cap 128 regs -> 16 warps/SM
void vqc_kernel(const float* __restrict__ h,
                const float* __restrict__ W,
                const float* __restrict__ bpre,
                const float* __restrict__ wts,
                float* __restrict__ out,
                int B)
{
    __shared__ float4 Wsh[NQ * IND / 4];        // 16 KB
    __shared__ float4 Msh[NQ][2];
    __shared__ float  Bsh[NQ];

    const int tid  = threadIdx.x;
    const int lane = tid & 31;
    const int wrp  = tid >> 5;

    // ---- start h loads FIRST (hidden behind W staging + barrier) ----
    const int e0 = (blockIdx.x * WPB + wrp) * M4;
    const float4* hr = reinterpret_cast<const float4*>(h) + (size_t)e0 * (IND / 4);
    float4 hv[M4 * 4];
    #pragma unroll
    for (int mm = 0; mm < M4; ++mm)
        #pragma unroll
        for (int k = 0; k < 4; ++k)
            hv[mm * 4 + k] = hr[mm * (IND / 4) + k * 32 + lane];

    // Stage W_pre into shared (coalesced; 1024 float4 over 256 threads)
    #pragma unroll
    for (int i = 0; i < (NQ * IND / 4) / TPB; ++i)
        Wsh[tid + i * TPB] = reinterpret_cast<const float4*>(W)[tid + i * TPB];

    // Batch-independent gate matrices M_w = Rz(g)*Ry(b)*Rx(a)
    if (tid < NQ) {
        Bsh[tid] = bpre[tid];
        float al = 0.5f * wts[tid * 3 + 0];
        float be = 0.5f * wts[tid * 3 + 1];
        float ga = 0.5f * wts[tid * 3 + 2];
        float sa, ca, sb, cb, sg, cg;
        sincosf(al, &sa, &ca);
        sincosf(be, &sb, &cb);
        sincosf(ga, &sg, &cg);
        float r00r =  cb * ca, r00i =  sb * sa;
        float r01r = -sb * ca, r01i = -cb * sa;
        float r10r =  sb * ca, r10i = -cb * sa;
        float r11r =  cb * ca, r11i = -sb * sa;
        Msh[tid][0] = make_float4(r00r * cg + r00i * sg,
                                  r00i * cg - r00r * sg,
                                  r01r * cg + r01i * sg,
                                  r01i * cg - r01r * sg);
        Msh[tid][1] = make_float4(r10r * cg - r10i * sg,
                                  r10i * cg + r10r * sg,
                                  r11r * cg - r11i * sg,
                                  r11i * cg + r11r * sg);
    }
    __syncthreads();

    const int w = lane >> 2;      // qubit owned by this lane after reduction
    const int m = lane & 3;       // element owned by this lane

    // ---------- GEMM: r[o*4+mm] = <h[e0+mm], W[o]> (lane's K-slice) ----------
    float r[32];
    #pragma unroll
    for (int i = 0; i < 32; ++i) r[i] = 0.f;

    #pragma unroll
    for (int k = 0; k < 4; ++k) {
        #pragma unroll
        for (int o = 0; o < NQ; ++o) {
            float4 wv = Wsh[o * (IND / 4) + k * 32 + lane];
            #pragma unroll
            for (int mm = 0; mm < M4; ++mm) {
                float4 hx = hv[mm * 4 + k];
                r[o * 4 + mm] = fmaf(hx.x, wv.x, fmaf(hx.y, wv.y,
                                fmaf(hx.z, wv.z, fmaf(hx.w, wv.w, r[o * 4 + mm]))));
            }
        }
    }

    // ---------- exchange-tree reduce: lane L ends with full sum of r[L] ----------
    #pragma unroll
    for (int s = 4; s >= 0; --s) {
        const int d = 1 << s;
        const bool hi = (lane >> s) & 1;
        #pragma unroll
        for (int j = 0; j < d; ++j) {
            float keep = hi ? r[j + d] : r[j];
            float send = hi ? r[j] : r[j + d];
            keep += __shfl_xor_sync(FULL, send, d);
            r[j] = keep;
        }
    }
    float a = r[0];                // pre-activation for (qubit w, elem m)

    // ---------- single-qubit state & Pauli expectations ----------
    float t = tanhf(a + Bsh[w]) * 1.57079632679489662f;
    t = fminf(fmaxf(t, -3.14159265358979f), 3.14159265358979f);
    float s, c;
    sincosf(0.5f * t, &s, &c);
    float4 m0 = Msh[w][0], m1 = Msh[w][1];
    float v0r = m0.x * c + m0.z * s, v0i = m0.y * c + m0.w * s;
    float v1r = m1.x * c + m1.z * s, v1i = m1.y * c + m1.w * s;
    float x = 2.f * (v0r * v1r + v0i * v1i);
    float y = 2.f * (v0r * v1i - v0i * v1r);
    float z = (v0r * v0r + v0i * v0i) - (v1r * v1r + v1i * v1i);

    // ---------- product scans over the stride-4 lane comb (8 qubits) ----------
    float P = z;                   // inclusive prefix z0..zw
    float G = (w >= 2) ? z : 1.f;  // prefix of z restricted to w>=2
    #pragma unroll
    for (int d = 1; d < 8; d <<= 1) {
        float tp = __shfl_up_sync(FULL, P, 4 * d);
        float tg = __shfl_up_sync(FULL, G, 4 * d);
        if (w >= d) { P *= tp; G *= tg; }
    }
    float Pexc  = __shfl_up_sync(FULL, P, 4);                   // z0..z_{w-1}
    float xnext = __shfl_sync(FULL, x, m + 4 * ((w + 1) & 7));  // x_{w+1 mod 8}
    float x1    = __shfl_sync(FULL, x, m + 4);
    float y0    = __shfl_sync(FULL, y, m);
    float y1    = __shfl_sync(FULL, y, m + 4);
    float z1    = __shfl_sync(FULL, z, m + 4);
    float G6    = __shfl_sync(FULL, G, m + 24);                 // z2..z6
    float G7    = __shfl_sync(FULL, G, m + 28);                 // z2..z7

    // ---------- assemble the 3 observables this lane owns ----------
    float X = (w == 7) ? (x * xnext * x1) : (x * xnext);
    float Y, Z;
    if (w == 0)      { Y = x * y1 * G7;            Z = z1 * G7; }
    else if (w == 7) { Y = -y0 * y1 * G6 * y;      Z = P; }
    else             { Y = Pexc * y * xnext;       Z = P; }

    // ---------- normalize over the 24 outputs of this element ----------
    float ss = X * X + Y * Y + Z * Z;
    ss += __shfl_xor_sync(FULL, ss, 4);
    ss += __shfl_xor_sync(FULL, ss, 8);
    ss += __shfl_xor_sync(FULL, ss, 16);
    float inv = 1.f / fmaxf(sqrtf(ss), 1e-12f);

    int e = e0 + m;
    if (e < B) {
        float* op = out + (size_t)e * 24 + 3 * w;
        op[0] = X * inv;
        op[1] = Y * inv;
        op[2] = Z * inv;
    }
}

extern "C" void kernel_launch(void* const* d_in, const int* in_sizes, int n_in,
                              void* d_out, int out_size)
{
    const float* h    = (const float*)d_in[0];
    const float* W    = (const float*)d_in[1];
    const float* bpre = (const float*)d_in[2];
    const float* wts  = (const float*)d_in[3];
    float* out        = (float*)d_out;

    int B = in_sizes[0] / IND;                          // 16384
    int blocks = (B + WPB * M4 - 1) / (WPB * M4);       // 512 streaming blocks
    vqc_kernel<<<blocks, TPB>>>(h, W, bpre, wts, out, B);
}